// round 1
// baseline (speedup 1.0000x reference)
#include <cuda_runtime.h>
#include <cstdint>

// Problem: y = x @ W^T + b ; then per-token outlier-aware fake quant.
// x: [B,S,Din] f32, W: [Dout,Din] f32, b: [Dout] f32, out: [B,S,Dout] f32
// M = B*S = 16384, N = Dout = 2048, K = Din = 2048 (fixed shapes for this problem)

#define K_DIM 2048
#define N_DIM 2048

#define BM 128
#define BN 128
#define BK 8
#define TM 8
#define TN 8
// 256 threads per block: 16x16 thread tile of 8x8 accumulators

__global__ __launch_bounds__(256, 2)
void oal_gemm_kernel(const float* __restrict__ A,   // [M, K]
                     const float* __restrict__ W,   // [N, K]
                     const float* __restrict__ bias,// [N]
                     float* __restrict__ Y,         // [M, N]
                     int M) {
    __shared__ float As[BK][BM];
    __shared__ float Ws[BK][BN];

    const int tid = threadIdx.x;
    const int block_m = blockIdx.y * BM;
    const int block_n = blockIdx.x * BN;

    // gmem->smem load mapping: 256 threads, each loads one float4 from A-tile
    // and one from W-tile. Tile is 128 rows x 8 K. row = tid/2, k4 = (tid&1)*4
    const int lrow = tid >> 1;
    const int lcol = (tid & 1) * 4;

    const float* Aptr = A + (size_t)(block_m + lrow) * K_DIM + lcol;
    const float* Wptr = W + (size_t)(block_n + lrow) * K_DIM + lcol;

    const int trow = (tid >> 4) * TM;  // 0,8,...,120
    const int tcol = (tid & 15) * TN;  // 0,8,...,120

    float acc[TM][TN];
#pragma unroll
    for (int i = 0; i < TM; i++)
#pragma unroll
        for (int j = 0; j < TN; j++) acc[i][j] = 0.0f;

    for (int k0 = 0; k0 < K_DIM; k0 += BK) {
        float4 a4 = *reinterpret_cast<const float4*>(Aptr);
        float4 w4 = *reinterpret_cast<const float4*>(Wptr);
        As[lcol + 0][lrow] = a4.x;
        As[lcol + 1][lrow] = a4.y;
        As[lcol + 2][lrow] = a4.z;
        As[lcol + 3][lrow] = a4.w;
        Ws[lcol + 0][lrow] = w4.x;
        Ws[lcol + 1][lrow] = w4.y;
        Ws[lcol + 2][lrow] = w4.z;
        Ws[lcol + 3][lrow] = w4.w;
        __syncthreads();

#pragma unroll
        for (int k = 0; k < BK; k++) {
            float ar[TM], wr[TN];
            *reinterpret_cast<float4*>(&ar[0]) = *reinterpret_cast<const float4*>(&As[k][trow]);
            *reinterpret_cast<float4*>(&ar[4]) = *reinterpret_cast<const float4*>(&As[k][trow + 4]);
            *reinterpret_cast<float4*>(&wr[0]) = *reinterpret_cast<const float4*>(&Ws[k][tcol]);
            *reinterpret_cast<float4*>(&wr[4]) = *reinterpret_cast<const float4*>(&Ws[k][tcol + 4]);
#pragma unroll
            for (int i = 0; i < TM; i++)
#pragma unroll
                for (int j = 0; j < TN; j++)
                    acc[i][j] = fmaf(ar[i], wr[j], acc[i][j]);
        }
        __syncthreads();

        Aptr += BK;
        Wptr += BK;
    }

    // epilogue: add bias, store (all dims divide evenly; no bounds checks needed)
#pragma unroll
    for (int i = 0; i < TM; i++) {
        float* yrow = Y + (size_t)(block_m + trow + i) * N_DIM + block_n + tcol;
#pragma unroll
        for (int j4 = 0; j4 < TN; j4 += 4) {
            float4 v;
            v.x = acc[i][j4 + 0] + bias[block_n + tcol + j4 + 0];
            v.y = acc[i][j4 + 1] + bias[block_n + tcol + j4 + 1];
            v.z = acc[i][j4 + 2] + bias[block_n + tcol + j4 + 2];
            v.w = acc[i][j4 + 3] + bias[block_n + tcol + j4 + 3];
            *reinterpret_cast<float4*>(yrow + j4) = v;
        }
    }
}

// ---------------------------------------------------------------------------
// Per-token (row) outlier-aware quantization, in place on Y.
// One block of 256 threads per row of D=2048. Each thread owns 8 values
// (two float4 loads), kept in registers across the reduction.
// ---------------------------------------------------------------------------

#define QMAX 127.0f
#define OUTLIER_T 3.0f
#define Q_EPS 1e-6f

__global__ __launch_bounds__(256)
void oal_quant_kernel(float* __restrict__ Y) {
    const size_t row = blockIdx.x;
    float* y = Y + row * (size_t)N_DIM;
    float4* y4 = reinterpret_cast<float4*>(y);

    const int tid = threadIdx.x;
    float4 p = y4[tid];
    float4 q = y4[tid + 256];

    float v[8] = {p.x, p.y, p.z, p.w, q.x, q.y, q.z, q.w};

    float s = 0.0f, ss = 0.0f, amax = 0.0f;
#pragma unroll
    for (int i = 0; i < 8; i++) {
        s += v[i];
        ss = fmaf(v[i], v[i], ss);
        amax = fmaxf(amax, fabsf(v[i]));
    }

    // warp reduce (sum, sumsq, max)
#pragma unroll
    for (int off = 16; off > 0; off >>= 1) {
        s += __shfl_xor_sync(0xFFFFFFFFu, s, off);
        ss += __shfl_xor_sync(0xFFFFFFFFu, ss, off);
        amax = fmaxf(amax, __shfl_xor_sync(0xFFFFFFFFu, amax, off));
    }

    __shared__ float red_s[8], red_ss[8], red_m[8];
    const int wid = tid >> 5;
    const int lid = tid & 31;
    if (lid == 0) {
        red_s[wid] = s;
        red_ss[wid] = ss;
        red_m[wid] = amax;
    }
    __syncthreads();

    if (wid == 0) {
        float s2 = (lid < 8) ? red_s[lid] : 0.0f;
        float ss2 = (lid < 8) ? red_ss[lid] : 0.0f;
        float m2 = (lid < 8) ? red_m[lid] : 0.0f;
#pragma unroll
        for (int off = 4; off > 0; off >>= 1) {
            s2 += __shfl_xor_sync(0xFFFFFFFFu, s2, off);
            ss2 += __shfl_xor_sync(0xFFFFFFFFu, ss2, off);
            m2 = fmaxf(m2, __shfl_xor_sync(0xFFFFFFFFu, m2, off));
        }
        if (lid == 0) {
            red_s[0] = s2;
            red_ss[0] = ss2;
            red_m[0] = m2;
        }
    }
    __syncthreads();

    const float inv_d = 1.0f / (float)N_DIM;
    const float mean = red_s[0] * inv_d;
    const float var = fmaxf(red_ss[0] * inv_d - mean * mean, 0.0f);
    const float stdv = sqrtf(var);
    const float thr = OUTLIER_T * stdv;
    // max |clip(y,-thr,thr)| == min(absmax, thr)
    const float scale = fmaxf(fminf(red_m[0], thr) / QMAX, Q_EPS);
    const float inv_scale = 1.0f / scale;

#pragma unroll
    for (int i = 0; i < 8; i++) {
        float x = v[i];
        float c = fminf(fmaxf(x, -thr), thr);
        float fq = rintf(c * inv_scale) * scale;  // rintf = round half to even (matches jnp.round)
        v[i] = (fabsf(x) > thr) ? x : fq;
    }

    p.x = v[0]; p.y = v[1]; p.z = v[2]; p.w = v[3];
    q.x = v[4]; q.y = v[5]; q.z = v[6]; q.w = v[7];
    y4[tid] = p;
    y4[tid + 256] = q;
}

// ---------------------------------------------------------------------------

extern "C" void kernel_launch(void* const* d_in, const int* in_sizes, int n_in,
                              void* d_out, int out_size) {
    const float* x = (const float*)d_in[0];    // [B,S,Din]
    const float* W = (const float*)d_in[1];    // [Dout,Din]
    const float* b = (const float*)d_in[2];    // [Dout]
    float* out = (float*)d_out;                // [B,S,Dout]

    const int M = in_sizes[0] / K_DIM;         // 16384

    dim3 gblock(256);
    dim3 ggrid(N_DIM / BN, M / BM);            // (16, 128)
    oal_gemm_kernel<<<ggrid, gblock>>>(x, W, b, out, M);

    dim3 qgrid(M);
    oal_quant_kernel<<<qgrid, 256>>>(out);
}

// round 7
// speedup vs baseline: 1.5583x; 1.5583x over previous
#include <cuda_runtime.h>
#include <cstdint>

// ============================================================================
// OutlierAwareLinear on plain sm_100 target (no tcgen05 available):
//   y = x @ W^T + b  via 3xTF32 split on mma.sync.m16n8k8 (legacy tensor pipe),
//   then per-token outlier-aware fake quant.
// x: [16384,2048] f32, W: [2048,2048] f32, b: [2048] f32 -> out [16384,2048] f32
// ============================================================================

#define K_DIM 2048
#define N_DIM 2048
#define BM 128
#define BN 256
#define BK 32
#define NCHUNKS (K_DIM / BK)   // 64

// smem regions (per buffer): hi/lo split tiles, K-major, 128B rows, SW128 swizz
#define OFF_AHI 0
#define OFF_ALO 16384
#define OFF_BHI 32768
#define OFF_BLO 65536
#define BUF_STRIDE 98304
#define SMEM_TOTAL (2 * BUF_STRIDE)   // 192 KB

__device__ __forceinline__ uint32_t smem_u32(const void* p) {
    return (uint32_t)__cvta_generic_to_shared(p);
}
// cvt.rna.tf32.f32 takes a .b32 destination (fp32 bit pattern of the tf32 value)
__device__ __forceinline__ float tf32r(float x) {
    uint32_t r;
    asm("cvt.rna.tf32.f32 %0, %1;" : "=r"(r) : "f"(x));
    return __uint_as_float(r);
}
__device__ __forceinline__ uint32_t swz(uint32_t off) {
    return off ^ ((off >> 3) & 0x70);
}
__device__ __forceinline__ void ldsm_x4(uint32_t r[4], uint32_t addr) {
    asm volatile("ldmatrix.sync.aligned.m8n8.x4.shared.b16 {%0,%1,%2,%3}, [%4];"
                 : "=r"(r[0]), "=r"(r[1]), "=r"(r[2]), "=r"(r[3]) : "r"(addr));
}
__device__ __forceinline__ void mma_tf32(float c[4], const uint32_t a[4],
                                         const uint32_t* b) {
    asm volatile(
        "mma.sync.aligned.m16n8k8.row.col.f32.tf32.tf32.f32 "
        "{%0,%1,%2,%3}, {%4,%5,%6,%7}, {%8,%9}, {%0,%1,%2,%3};"
        : "+f"(c[0]), "+f"(c[1]), "+f"(c[2]), "+f"(c[3])
        : "r"(a[0]), "r"(a[1]), "r"(a[2]), "r"(a[3]), "r"(b[0]), "r"(b[1]));
}

// ---------------------------------------------------------------------------
// GEMM: CTA 128x256, 8 warps (4M x 2N), warp tile 32x128, 3xTF32 split.
// ---------------------------------------------------------------------------
__global__ __launch_bounds__(256, 1)
void oal_gemm_tf32(const float* __restrict__ A,    // [M,K]
                   const float* __restrict__ Wm,   // [N,K]
                   const float* __restrict__ bias, // [N]
                   float* __restrict__ Y) {        // [M,N]
    extern __shared__ char smem[];
    const uint32_t sb = smem_u32(smem);

    const int tid = threadIdx.x;
    const int lane = tid & 31;
    const int wid = tid >> 5;
    const int warp_m = (wid & 3) * 32;
    const int warp_n = (wid >> 2) * 128;
    const int block_m = blockIdx.y * BM;
    const int block_n = blockIdx.x * BN;

    // --- ldmatrix lane offsets, kept UNSWIZZLED; swizzle applied at use via
    //     XOR with swmask. The SW128 mask depends only on row&7, and every
    //     row stride here is a multiple of 8, so one mask per thread works.
    //     (Adding ks*32 AFTER swizzling carries into the row field -> OOB.
    //     Unswizzled base has bits 5-6 clear, so base + ks*32 never carries,
    //     and XOR keeps the address inside the 128-byte row.)
    const uint32_t swmask = (lane & 7) << 4;

    // A fragment tile (m16 x k8): lanes 0-15 -> kcols 0-3, lanes 16-31 -> kcols 4-7
    uint32_t a_off[2];
#pragma unroll
    for (int mt = 0; mt < 2; mt++) {
        uint32_t row = warp_m + mt * 16 + (lane & 15);
        a_off[mt] = row * 128 + (lane >> 4) * 16;   // unswizzled
    }
    // B: each ldsm.x4 covers 2 n-tiles (8 rows each) x 2 k-halves
    uint32_t b_off[8];
#pragma unroll
    for (int ntp = 0; ntp < 8; ntp++) {
        uint32_t n = warp_n + ntp * 16 + ((lane >> 4) & 1) * 8 + (lane & 7);
        b_off[ntp] = n * 128 + ((lane >> 3) & 1) * 16;   // unswizzled
    }

    // --- producer addressing ---
    const int r8 = tid >> 3;            // 0..31
    const int c8 = (tid & 7) * 16;      // byte col of float4 in 128B row
    const float* Abase = A + (size_t)(block_m + r8) * K_DIM + (tid & 7) * 4;
    const float* Bbase = Wm + (size_t)(block_n + r8) * K_DIM + (tid & 7) * 4;

    float acc[2][16][4];
#pragma unroll
    for (int mt = 0; mt < 2; mt++)
#pragma unroll
        for (int nt = 0; nt < 16; nt++)
#pragma unroll
            for (int j = 0; j < 4; j++) acc[mt][nt][j] = 0.0f;

    float4 av[4], bv[8];

    // ---- prologue: load + split + store chunk 0 ----
#pragma unroll
    for (int p = 0; p < 4; p++) av[p] = *(const float4*)(Abase + (size_t)(p * 32) * K_DIM);
#pragma unroll
    for (int p = 0; p < 8; p++) bv[p] = *(const float4*)(Bbase + (size_t)(p * 32) * K_DIM);

    {
        char* dst = smem;  // buffer 0
#pragma unroll
        for (int p = 0; p < 4; p++) {
            uint32_t sw = swz((r8 + p * 32) * 128 + c8);
            float4 hi, lo;
            hi.x = tf32r(av[p].x); lo.x = tf32r(av[p].x - hi.x);
            hi.y = tf32r(av[p].y); lo.y = tf32r(av[p].y - hi.y);
            hi.z = tf32r(av[p].z); lo.z = tf32r(av[p].z - hi.z);
            hi.w = tf32r(av[p].w); lo.w = tf32r(av[p].w - hi.w);
            *(float4*)(dst + OFF_AHI + sw) = hi;
            *(float4*)(dst + OFF_ALO + sw) = lo;
        }
#pragma unroll
        for (int p = 0; p < 8; p++) {
            uint32_t sw = swz((r8 + p * 32) * 128 + c8);
            float4 hi, lo;
            hi.x = tf32r(bv[p].x); lo.x = tf32r(bv[p].x - hi.x);
            hi.y = tf32r(bv[p].y); lo.y = tf32r(bv[p].y - hi.y);
            hi.z = tf32r(bv[p].z); lo.z = tf32r(bv[p].z - hi.z);
            hi.w = tf32r(bv[p].w); lo.w = tf32r(bv[p].w - hi.w);
            *(float4*)(dst + OFF_BHI + sw) = hi;
            *(float4*)(dst + OFF_BLO + sw) = lo;
        }
    }
    __syncthreads();

    // ---- main loop ----
    for (int c = 0; c < NCHUNKS; c++) {
        const uint32_t cur = sb + (c & 1) * BUF_STRIDE;

        // prefetch next chunk into regs (hidden under the mma phase)
        if (c + 1 < NCHUNKS) {
            const int k0 = (c + 1) * BK;
#pragma unroll
            for (int p = 0; p < 4; p++)
                av[p] = *(const float4*)(Abase + (size_t)(p * 32) * K_DIM + k0);
#pragma unroll
            for (int p = 0; p < 8; p++)
                bv[p] = *(const float4*)(Bbase + (size_t)(p * 32) * K_DIM + k0);
        }

        // mma phase over current buffer
#pragma unroll
        for (int ks = 0; ks < 4; ks++) {
            uint32_t ah[2][4], al[2][4];
#pragma unroll
            for (int mt = 0; mt < 2; mt++) {
                const uint32_t ao = (a_off[mt] + ks * 32) ^ swmask;
                ldsm_x4(ah[mt], cur + OFF_AHI + ao);
                ldsm_x4(al[mt], cur + OFF_ALO + ao);
            }
#pragma unroll
            for (int ntp = 0; ntp < 8; ntp++) {
                const uint32_t bo = (b_off[ntp] + ks * 32) ^ swmask;
                uint32_t bh[4], bl[4];
                ldsm_x4(bh, cur + OFF_BHI + bo);
                ldsm_x4(bl, cur + OFF_BLO + bo);
#pragma unroll
                for (int t = 0; t < 2; t++) {
                    const int nt = 2 * ntp + t;
#pragma unroll
                    for (int mt = 0; mt < 2; mt++) {
                        mma_tf32(acc[mt][nt], ah[mt], bh + 2 * t);  // hi*hi
                        mma_tf32(acc[mt][nt], ah[mt], bl + 2 * t);  // hi*lo
                        mma_tf32(acc[mt][nt], al[mt], bh + 2 * t);  // lo*hi
                    }
                }
            }
        }

        // split + store next chunk into the other buffer
        if (c + 1 < NCHUNKS) {
            char* dst = smem + ((c + 1) & 1) * BUF_STRIDE;
#pragma unroll
            for (int p = 0; p < 4; p++) {
                uint32_t sw = swz((r8 + p * 32) * 128 + c8);
                float4 hi, lo;
                hi.x = tf32r(av[p].x); lo.x = tf32r(av[p].x - hi.x);
                hi.y = tf32r(av[p].y); lo.y = tf32r(av[p].y - hi.y);
                hi.z = tf32r(av[p].z); lo.z = tf32r(av[p].z - hi.z);
                hi.w = tf32r(av[p].w); lo.w = tf32r(av[p].w - hi.w);
                *(float4*)(dst + OFF_AHI + sw) = hi;
                *(float4*)(dst + OFF_ALO + sw) = lo;
            }
#pragma unroll
            for (int p = 0; p < 8; p++) {
                uint32_t sw = swz((r8 + p * 32) * 128 + c8);
                float4 hi, lo;
                hi.x = tf32r(bv[p].x); lo.x = tf32r(bv[p].x - hi.x);
                hi.y = tf32r(bv[p].y); lo.y = tf32r(bv[p].y - hi.y);
                hi.z = tf32r(bv[p].z); lo.z = tf32r(bv[p].z - hi.z);
                hi.w = tf32r(bv[p].w); lo.w = tf32r(bv[p].w - hi.w);
                *(float4*)(dst + OFF_BHI + sw) = hi;
                *(float4*)(dst + OFF_BLO + sw) = lo;
            }
        }
        __syncthreads();
    }

    // ---- epilogue: acc -> gmem with bias ----
    const int g = lane >> 2;
    const int t4 = lane & 3;
#pragma unroll
    for (int mt = 0; mt < 2; mt++) {
        const int m0 = block_m + warp_m + mt * 16 + g;
#pragma unroll
        for (int nt = 0; nt < 16; nt++) {
            const int n0 = block_n + warp_n + nt * 8 + t4 * 2;
            const float2 bb = *(const float2*)(bias + n0);
            float2 v0, v1;
            v0.x = acc[mt][nt][0] + bb.x;
            v0.y = acc[mt][nt][1] + bb.y;
            v1.x = acc[mt][nt][2] + bb.x;
            v1.y = acc[mt][nt][3] + bb.y;
            *(float2*)(Y + (size_t)m0 * N_DIM + n0) = v0;
            *(float2*)(Y + (size_t)(m0 + 8) * N_DIM + n0) = v1;
        }
    }
}

// ---------------------------------------------------------------------------
// Per-token outlier-aware fake quant (66% of HBM peak already).
// ---------------------------------------------------------------------------
#define QMAX 127.0f
#define OUTLIER_T 3.0f
#define Q_EPS 1e-6f

__global__ __launch_bounds__(256)
void oal_quant_kernel(float* __restrict__ Y) {
    const size_t row = blockIdx.x;
    float4* y4 = reinterpret_cast<float4*>(Y + row * (size_t)N_DIM);

    const int tid = threadIdx.x;
    float4 p = y4[tid];
    float4 q = y4[tid + 256];
    float v[8] = {p.x, p.y, p.z, p.w, q.x, q.y, q.z, q.w};

    float s = 0.0f, ss = 0.0f, amax = 0.0f;
#pragma unroll
    for (int i = 0; i < 8; i++) {
        s += v[i];
        ss = fmaf(v[i], v[i], ss);
        amax = fmaxf(amax, fabsf(v[i]));
    }
#pragma unroll
    for (int off = 16; off > 0; off >>= 1) {
        s += __shfl_xor_sync(0xFFFFFFFFu, s, off);
        ss += __shfl_xor_sync(0xFFFFFFFFu, ss, off);
        amax = fmaxf(amax, __shfl_xor_sync(0xFFFFFFFFu, amax, off));
    }

    __shared__ float red_s[8], red_ss[8], red_m[8];
    const int wid = tid >> 5;
    const int lid = tid & 31;
    if (lid == 0) { red_s[wid] = s; red_ss[wid] = ss; red_m[wid] = amax; }
    __syncthreads();

    if (wid == 0) {
        float s2 = (lid < 8) ? red_s[lid] : 0.0f;
        float ss2 = (lid < 8) ? red_ss[lid] : 0.0f;
        float m2 = (lid < 8) ? red_m[lid] : 0.0f;
#pragma unroll
        for (int off = 4; off > 0; off >>= 1) {
            s2 += __shfl_xor_sync(0xFFFFFFFFu, s2, off);
            ss2 += __shfl_xor_sync(0xFFFFFFFFu, ss2, off);
            m2 = fmaxf(m2, __shfl_xor_sync(0xFFFFFFFFu, m2, off));
        }
        if (lid == 0) { red_s[0] = s2; red_ss[0] = ss2; red_m[0] = m2; }
    }
    __syncthreads();

    const float inv_d = 1.0f / (float)N_DIM;
    const float mean = red_s[0] * inv_d;
    const float var = fmaxf(red_ss[0] * inv_d - mean * mean, 0.0f);
    const float thr = OUTLIER_T * sqrtf(var);
    const float scale = fmaxf(fminf(red_m[0], thr) / QMAX, Q_EPS);
    const float inv_scale = 1.0f / scale;

#pragma unroll
    for (int i = 0; i < 8; i++) {
        float x = v[i];
        float cl = fminf(fmaxf(x, -thr), thr);
        float fq = rintf(cl * inv_scale) * scale;
        v[i] = (fabsf(x) > thr) ? x : fq;
    }

    p.x = v[0]; p.y = v[1]; p.z = v[2]; p.w = v[3];
    q.x = v[4]; q.y = v[5]; q.z = v[6]; q.w = v[7];
    y4[tid] = p;
    y4[tid + 256] = q;
}

// ---------------------------------------------------------------------------

extern "C" void kernel_launch(void* const* d_in, const int* in_sizes, int n_in,
                              void* d_out, int out_size) {
    const float* x = (const float*)d_in[0];
    const float* W = (const float*)d_in[1];
    const float* b = (const float*)d_in[2];
    float* out = (float*)d_out;

    const int M = in_sizes[0] / K_DIM;   // 16384

    cudaFuncSetAttribute(oal_gemm_tf32, cudaFuncAttributeMaxDynamicSharedMemorySize, SMEM_TOTAL);

    dim3 ggrid(N_DIM / BN, M / BM);      // (8, 128)
    oal_gemm_tf32<<<ggrid, 256, SMEM_TOTAL>>>(x, W, b, out);

    oal_quant_kernel<<<M, 256>>>(out);
}

// round 8
// speedup vs baseline: 3.4658x; 2.2241x over previous
#include <cuda_runtime.h>
#include <cuda_fp16.h>
#include <cstdint>

// ============================================================================
// OutlierAwareLinear: y = x @ W^T + b, then per-token outlier-aware fake quant.
// GEMM via 3-term FP16 split (hi/lo) on mma.sync.m16n8k16.f16.f32:
//   a*b ~= ah*bh + ah*bl + al*bh   (al*bl ~ 2^-22 dropped; fp32-like accuracy)
// x,W pre-split once into __device__ fp16 hi/lo arrays; GEMM streams them via
// cp.async (no register staging, no in-loop conversion).
// ============================================================================

#define M_DIM 16384
#define K_DIM 2048
#define N_DIM 2048
#define BM 128
#define BN 256
#define BK 64                    // 64 fp16 = 128 bytes per row
#define NCHUNKS (K_DIM / BK)     // 32

// smem per buffer: Ahi 16K | Alo 16K | Bhi 32K | Blo 32K = 96KB; 2 buffers
#define OFF_AHI 0
#define OFF_ALO 16384
#define OFF_BHI 32768
#define OFF_BLO 65536
#define BUF_STRIDE 98304
#define SMEM_TOTAL (2 * BUF_STRIDE)   // 192 KB

// ---- global fp16 hi/lo scratch (static __device__ arrays; no runtime alloc) ----
__device__ __half g_Ahi[(size_t)M_DIM * K_DIM];   // 64 MB
__device__ __half g_Alo[(size_t)M_DIM * K_DIM];   // 64 MB
__device__ __half g_Whi[(size_t)N_DIM * K_DIM];   // 8 MB
__device__ __half g_Wlo[(size_t)N_DIM * K_DIM];   // 8 MB

__device__ __forceinline__ uint32_t smem_u32(const void* p) {
    return (uint32_t)__cvta_generic_to_shared(p);
}
__device__ __forceinline__ uint32_t swz(uint32_t off) {
    return off ^ ((off >> 3) & 0x70);
}
__device__ __forceinline__ void ldsm_x4(uint32_t r[4], uint32_t addr) {
    asm volatile("ldmatrix.sync.aligned.m8n8.x4.shared.b16 {%0,%1,%2,%3}, [%4];"
                 : "=r"(r[0]), "=r"(r[1]), "=r"(r[2]), "=r"(r[3]) : "r"(addr));
}
__device__ __forceinline__ void mma_f16(float c[4], const uint32_t a[4],
                                        const uint32_t* b) {
    asm volatile(
        "mma.sync.aligned.m16n8k16.row.col.f32.f16.f16.f32 "
        "{%0,%1,%2,%3}, {%4,%5,%6,%7}, {%8,%9}, {%0,%1,%2,%3};"
        : "+f"(c[0]), "+f"(c[1]), "+f"(c[2]), "+f"(c[3])
        : "r"(a[0]), "r"(a[1]), "r"(a[2]), "r"(a[3]), "r"(b[0]), "r"(b[1]));
}
__device__ __forceinline__ void cp16(uint32_t dst, const void* src) {
    asm volatile("cp.async.cg.shared.global [%0], [%1], 16;" :: "r"(dst), "l"(src));
}
#define CP_COMMIT() asm volatile("cp.async.commit_group;" ::: "memory")
#define CP_WAIT1()  asm volatile("cp.async.wait_group 1;" ::: "memory")

// ---------------------------------------------------------------------------
// Split kernel: x and W -> fp16 (hi, lo). One float4 per thread.
// ---------------------------------------------------------------------------
#define NX4 ((size_t)M_DIM * K_DIM / 4)
#define NW4 ((size_t)N_DIM * K_DIM / 4)

__global__ __launch_bounds__(256)
void oal_split_kernel(const float4* __restrict__ x4, const float4* __restrict__ w4) {
    const size_t i = (size_t)blockIdx.x * blockDim.x + threadIdx.x;
    float4 v;
    __half2 *hi, *lo;
    size_t o;
    if (i < NX4) {
        v = x4[i];
        hi = (__half2*)g_Ahi; lo = (__half2*)g_Alo; o = i * 2;
    } else if (i < NX4 + NW4) {
        v = w4[i - NX4];
        hi = (__half2*)g_Whi; lo = (__half2*)g_Wlo; o = (i - NX4) * 2;
    } else return;

    __half hx = __float2half_rn(v.x), hy = __float2half_rn(v.y);
    __half hz = __float2half_rn(v.z), hw = __float2half_rn(v.w);
    __half lx = __float2half_rn(v.x - __half2float(hx));
    __half ly = __float2half_rn(v.y - __half2float(hy));
    __half lz = __float2half_rn(v.z - __half2float(hz));
    __half lw = __float2half_rn(v.w - __half2float(hw));
    hi[o]     = __halves2half2(hx, hy);
    hi[o + 1] = __halves2half2(hz, hw);
    lo[o]     = __halves2half2(lx, ly);
    lo[o + 1] = __halves2half2(lz, lw);
}

// ---------------------------------------------------------------------------
// GEMM: CTA 128x256, 8 warps (4M x 2N), warp tile 32x128, fp16 hi/lo 3-term.
// ---------------------------------------------------------------------------
__global__ __launch_bounds__(256, 1)
void oal_gemm_f16(const float* __restrict__ bias, float* __restrict__ Y) {
    extern __shared__ char smem[];
    const uint32_t sb = smem_u32(smem);

    const int tid = threadIdx.x;
    const int lane = tid & 31;
    const int wid = tid >> 5;
    const int warp_m = (wid & 3) * 32;
    const int warp_n = (wid >> 2) * 128;
    const int block_m = blockIdx.y * BM;
    const int block_n = blockIdx.x * BN;

    // ldmatrix lane offsets (unswizzled; swizzle via XOR at use — same scheme
    // proven in R7; 16B seg = k0-7, +16B = k8-15, per-ks stride 32B = k16)
    const uint32_t swmask = (lane & 7) << 4;
    uint32_t a_off[2];
#pragma unroll
    for (int mt = 0; mt < 2; mt++) {
        uint32_t row = warp_m + mt * 16 + (lane & 15);
        a_off[mt] = row * 128 + (lane >> 4) * 16;
    }
    uint32_t b_off[8];
#pragma unroll
    for (int ntp = 0; ntp < 8; ntp++) {
        uint32_t n = warp_n + ntp * 16 + ((lane >> 4) & 1) * 8 + (lane & 7);
        b_off[ntp] = n * 128 + ((lane >> 3) & 1) * 16;
    }

    // producer: thread covers rows r8+32p, 16-byte seg (tid&7) of each 128B row
    const int r8 = tid >> 3;
    const int c16 = (tid & 7) * 16;            // byte offset in row
    const int kseg = (tid & 7) * 8;            // fp16 element offset in K

    const __half* Ahi = g_Ahi + (size_t)(block_m + r8) * K_DIM + kseg;
    const __half* Alo = g_Alo + (size_t)(block_m + r8) * K_DIM + kseg;
    const __half* Bhi = g_Whi + (size_t)(block_n + r8) * K_DIM + kseg;
    const __half* Blo = g_Wlo + (size_t)(block_n + r8) * K_DIM + kseg;

    float acc[2][16][4];
#pragma unroll
    for (int mt = 0; mt < 2; mt++)
#pragma unroll
        for (int nt = 0; nt < 16; nt++)
#pragma unroll
            for (int j = 0; j < 4; j++) acc[mt][nt][j] = 0.0f;

    // fill chunk c into buffer b (24 x cp.async 16B per thread)
    auto fill = [&](int c, int b) {
        const uint32_t base = sb + b * BUF_STRIDE;
        const int k0 = c * BK;
#pragma unroll
        for (int p = 0; p < 4; p++) {
            const uint32_t sw = swz((r8 + p * 32) * 128 + c16);
            cp16(base + OFF_AHI + sw, Ahi + (size_t)(p * 32) * K_DIM + k0);
            cp16(base + OFF_ALO + sw, Alo + (size_t)(p * 32) * K_DIM + k0);
        }
#pragma unroll
        for (int p = 0; p < 8; p++) {
            const uint32_t sw = swz((r8 + p * 32) * 128 + c16);
            cp16(base + OFF_BHI + sw, Bhi + (size_t)(p * 32) * K_DIM + k0);
            cp16(base + OFF_BLO + sw, Blo + (size_t)(p * 32) * K_DIM + k0);
        }
    };

    fill(0, 0); CP_COMMIT();
    fill(1, 1); CP_COMMIT();

    for (int c = 0; c < NCHUNKS; c++) {
        const int b = c & 1;
        const uint32_t cur = sb + b * BUF_STRIDE;

        CP_WAIT1();           // group for buffer b complete
        __syncthreads();

#pragma unroll
        for (int ks = 0; ks < 4; ks++) {
            uint32_t ah[2][4], al[2][4];
#pragma unroll
            for (int mt = 0; mt < 2; mt++) {
                const uint32_t ao = (a_off[mt] + ks * 32) ^ swmask;
                ldsm_x4(ah[mt], cur + OFF_AHI + ao);
                ldsm_x4(al[mt], cur + OFF_ALO + ao);
            }
#pragma unroll
            for (int ntp = 0; ntp < 8; ntp++) {
                const uint32_t bo = (b_off[ntp] + ks * 32) ^ swmask;
                uint32_t bh[4], bl[4];
                ldsm_x4(bh, cur + OFF_BHI + bo);
                ldsm_x4(bl, cur + OFF_BLO + bo);
#pragma unroll
                for (int t = 0; t < 2; t++) {
                    const int nt = 2 * ntp + t;
#pragma unroll
                    for (int mt = 0; mt < 2; mt++) {
                        mma_f16(acc[mt][nt], ah[mt], bh + 2 * t);  // hi*hi
                        mma_f16(acc[mt][nt], ah[mt], bl + 2 * t);  // hi*lo
                        mma_f16(acc[mt][nt], al[mt], bh + 2 * t);  // lo*hi
                    }
                }
            }
        }

        __syncthreads();      // all warps done reading buffer b
        if (c + 2 < NCHUNKS) fill(c + 2, b);
        CP_COMMIT();          // commit (possibly empty) to keep group counts aligned
    }

    // ---- epilogue: acc -> gmem with bias ----
    const int g = lane >> 2;
    const int t4 = lane & 3;
#pragma unroll
    for (int mt = 0; mt < 2; mt++) {
        const int m0 = block_m + warp_m + mt * 16 + g;
#pragma unroll
        for (int nt = 0; nt < 16; nt++) {
            const int n0 = block_n + warp_n + nt * 8 + t4 * 2;
            const float2 bb = *(const float2*)(bias + n0);
            float2 v0, v1;
            v0.x = acc[mt][nt][0] + bb.x;
            v0.y = acc[mt][nt][1] + bb.y;
            v1.x = acc[mt][nt][2] + bb.x;
            v1.y = acc[mt][nt][3] + bb.y;
            *(float2*)(Y + (size_t)m0 * N_DIM + n0) = v0;
            *(float2*)(Y + (size_t)(m0 + 8) * N_DIM + n0) = v1;
        }
    }
}

// ---------------------------------------------------------------------------
// Per-token outlier-aware fake quant (66% of HBM peak).
// ---------------------------------------------------------------------------
#define QMAX 127.0f
#define OUTLIER_T 3.0f
#define Q_EPS 1e-6f

__global__ __launch_bounds__(256)
void oal_quant_kernel(float* __restrict__ Y) {
    const size_t row = blockIdx.x;
    float4* y4 = reinterpret_cast<float4*>(Y + row * (size_t)N_DIM);

    const int tid = threadIdx.x;
    float4 p = y4[tid];
    float4 q = y4[tid + 256];
    float v[8] = {p.x, p.y, p.z, p.w, q.x, q.y, q.z, q.w};

    float s = 0.0f, ss = 0.0f, amax = 0.0f;
#pragma unroll
    for (int i = 0; i < 8; i++) {
        s += v[i];
        ss = fmaf(v[i], v[i], ss);
        amax = fmaxf(amax, fabsf(v[i]));
    }
#pragma unroll
    for (int off = 16; off > 0; off >>= 1) {
        s += __shfl_xor_sync(0xFFFFFFFFu, s, off);
        ss += __shfl_xor_sync(0xFFFFFFFFu, ss, off);
        amax = fmaxf(amax, __shfl_xor_sync(0xFFFFFFFFu, amax, off));
    }

    __shared__ float red_s[8], red_ss[8], red_m[8];
    const int wid = tid >> 5;
    const int lid = tid & 31;
    if (lid == 0) { red_s[wid] = s; red_ss[wid] = ss; red_m[wid] = amax; }
    __syncthreads();

    if (wid == 0) {
        float s2 = (lid < 8) ? red_s[lid] : 0.0f;
        float ss2 = (lid < 8) ? red_ss[lid] : 0.0f;
        float m2 = (lid < 8) ? red_m[lid] : 0.0f;
#pragma unroll
        for (int off = 4; off > 0; off >>= 1) {
            s2 += __shfl_xor_sync(0xFFFFFFFFu, s2, off);
            ss2 += __shfl_xor_sync(0xFFFFFFFFu, ss2, off);
            m2 = fmaxf(m2, __shfl_xor_sync(0xFFFFFFFFu, m2, off));
        }
        if (lid == 0) { red_s[0] = s2; red_ss[0] = ss2; red_m[0] = m2; }
    }
    __syncthreads();

    const float inv_d = 1.0f / (float)N_DIM;
    const float mean = red_s[0] * inv_d;
    const float var = fmaxf(red_ss[0] * inv_d - mean * mean, 0.0f);
    const float thr = OUTLIER_T * sqrtf(var);
    const float scale = fmaxf(fminf(red_m[0], thr) / QMAX, Q_EPS);
    const float inv_scale = 1.0f / scale;

#pragma unroll
    for (int i = 0; i < 8; i++) {
        float x = v[i];
        float cl = fminf(fmaxf(x, -thr), thr);
        float fq = rintf(cl * inv_scale) * scale;
        v[i] = (fabsf(x) > thr) ? x : fq;
    }

    p.x = v[0]; p.y = v[1]; p.z = v[2]; p.w = v[3];
    q.x = v[4]; q.y = v[5]; q.z = v[6]; q.w = v[7];
    y4[tid] = p;
    y4[tid + 256] = q;
}

// Tiny tail kernel: pads the replay to 4 launches so ncu's "-s 5 -c 1"
// lands on the GEMM (launch #2 of replay 2) instead of always the quant pass.
__global__ void oal_nop_kernel() {}

// ---------------------------------------------------------------------------

extern "C" void kernel_launch(void* const* d_in, const int* in_sizes, int n_in,
                              void* d_out, int out_size) {
    const float* x = (const float*)d_in[0];
    const float* W = (const float*)d_in[1];
    const float* b = (const float*)d_in[2];
    float* out = (float*)d_out;

    cudaFuncSetAttribute(oal_gemm_f16, cudaFuncAttributeMaxDynamicSharedMemorySize, SMEM_TOTAL);

    // 1) split x and W into fp16 hi/lo
    const size_t total4 = NX4 + NW4;
    const int sblocks = (int)((total4 + 255) / 256);
    oal_split_kernel<<<sblocks, 256>>>((const float4*)x, (const float4*)W);

    // 2) GEMM (launch #2 per replay -> ncu -s 5 captures this one)
    dim3 ggrid(N_DIM / BN, M_DIM / BM);   // (8, 128)
    oal_gemm_f16<<<ggrid, 256, SMEM_TOTAL>>>(b, out);

    // 3) per-token quant
    oal_quant_kernel<<<M_DIM, 256>>>(out);

    // 4) nop to make replays 4 launches long (ncu alignment)
    oal_nop_kernel<<<1, 32>>>();
}

// round 9
// speedup vs baseline: 3.5310x; 1.0188x over previous
#include <cuda_runtime.h>
#include <cuda_fp16.h>
#include <cstdint>

// ============================================================================
// OutlierAwareLinear: y = x @ W^T + b, then per-token outlier-aware fake quant.
// GEMM via 3-term FP16 split (hi/lo) on mma.sync.m16n8k16.f16.f32:
//   a*b ~= ah*bh + ah*bl + al*bh   (al*bl ~ 2^-22 dropped; fp32-like accuracy)
// W pre-split once into __device__ fp16 hi/lo arrays (16 MB, ~5us) -> cp.async.
// A (x) split in-GEMM from fp32 (register split staged 3 chunks ahead), saving
// the 256 MB x-split traffic (~40us) of the previous round.
// ============================================================================

#define M_DIM 16384
#define K_DIM 2048
#define N_DIM 2048
#define BM 128
#define BN 256
#define BK 64                    // 64 fp16 = 128 bytes per row
#define NCHUNKS (K_DIM / BK)     // 32

// smem per buffer: Ahi 16K | Alo 16K | Bhi 32K | Blo 32K = 96KB; 2 buffers
#define OFF_AHI 0
#define OFF_ALO 16384
#define OFF_BHI 32768
#define OFF_BLO 65536
#define BUF_STRIDE 98304
#define SMEM_TOTAL (2 * BUF_STRIDE)   // 192 KB

// ---- global fp16 hi/lo scratch for W only (static; no runtime alloc) ----
__device__ __half g_Whi[(size_t)N_DIM * K_DIM];   // 8 MB
__device__ __half g_Wlo[(size_t)N_DIM * K_DIM];   // 8 MB

__device__ __forceinline__ uint32_t smem_u32(const void* p) {
    return (uint32_t)__cvta_generic_to_shared(p);
}
__device__ __forceinline__ uint32_t swz(uint32_t off) {
    return off ^ ((off >> 3) & 0x70);
}
__device__ __forceinline__ void ldsm_x4(uint32_t r[4], uint32_t addr) {
    asm volatile("ldmatrix.sync.aligned.m8n8.x4.shared.b16 {%0,%1,%2,%3}, [%4];"
                 : "=r"(r[0]), "=r"(r[1]), "=r"(r[2]), "=r"(r[3]) : "r"(addr));
}
__device__ __forceinline__ void mma_f16(float c[4], const uint32_t a[4],
                                        const uint32_t* b) {
    asm volatile(
        "mma.sync.aligned.m16n8k16.row.col.f32.f16.f16.f32 "
        "{%0,%1,%2,%3}, {%4,%5,%6,%7}, {%8,%9}, {%0,%1,%2,%3};"
        : "+f"(c[0]), "+f"(c[1]), "+f"(c[2]), "+f"(c[3])
        : "r"(a[0]), "r"(a[1]), "r"(a[2]), "r"(a[3]), "r"(b[0]), "r"(b[1]));
}
__device__ __forceinline__ void cp16(uint32_t dst, const void* src) {
    asm volatile("cp.async.cg.shared.global [%0], [%1], 16;" :: "r"(dst), "l"(src));
}
#define CP_COMMIT() asm volatile("cp.async.commit_group;" ::: "memory")
#define CP_WAIT1()  asm volatile("cp.async.wait_group 1;" ::: "memory")

// ---------------------------------------------------------------------------
// W split kernel: W -> fp16 (hi, lo). One float4 per thread. ~16 MB total.
// ---------------------------------------------------------------------------
#define NW4 ((size_t)N_DIM * K_DIM / 4)

__global__ __launch_bounds__(256)
void oal_wsplit_kernel(const float4* __restrict__ w4) {
    const size_t i = (size_t)blockIdx.x * blockDim.x + threadIdx.x;
    if (i >= NW4) return;
    float4 v = w4[i];
    __half2* hi = (__half2*)g_Whi;
    __half2* lo = (__half2*)g_Wlo;
    const size_t o = i * 2;

    __half2 h0 = __floats2half2_rn(v.x, v.y);
    __half2 h1 = __floats2half2_rn(v.z, v.w);
    float2 f0 = __half22float2(h0);
    float2 f1 = __half22float2(h1);
    hi[o]     = h0;
    hi[o + 1] = h1;
    lo[o]     = __floats2half2_rn(v.x - f0.x, v.y - f0.y);
    lo[o + 1] = __floats2half2_rn(v.z - f1.x, v.w - f1.y);
}

// ---------------------------------------------------------------------------
// GEMM: CTA 128x256, 8 warps (4M x 2N), warp tile 32x128, fp16 hi/lo 3-term.
// B via cp.async from pre-split g_W*; A split in-kernel from fp32.
// ---------------------------------------------------------------------------
__global__ __launch_bounds__(256, 1)
void oal_gemm_f16(const float* __restrict__ A,     // [M,K] fp32
                  const float* __restrict__ bias,
                  float* __restrict__ Y) {
    extern __shared__ char smem[];
    const uint32_t sb = smem_u32(smem);

    const int tid = threadIdx.x;
    const int lane = tid & 31;
    const int wid = tid >> 5;
    const int warp_m = (wid & 3) * 32;
    const int warp_n = (wid >> 2) * 128;
    const int block_m = blockIdx.y * BM;
    const int block_n = blockIdx.x * BN;

    // ldmatrix lane offsets (unswizzled; swizzle via XOR at use — proven R7/R8)
    const uint32_t swmask = (lane & 7) << 4;
    uint32_t a_off[2];
#pragma unroll
    for (int mt = 0; mt < 2; mt++) {
        uint32_t row = warp_m + mt * 16 + (lane & 15);
        a_off[mt] = row * 128 + (lane >> 4) * 16;
    }
    uint32_t b_off[8];
#pragma unroll
    for (int ntp = 0; ntp < 8; ntp++) {
        uint32_t n = warp_n + ntp * 16 + ((lane >> 4) & 1) * 8 + (lane & 7);
        b_off[ntp] = n * 128 + ((lane >> 3) & 1) * 16;
    }

    // producer: thread owns rows {r8+32p}, 16-byte smem seg (tid&7) per row
    const int r8 = tid >> 3;
    const int c16 = (tid & 7) * 16;            // byte offset in 128B smem row
    const int kseg8 = (tid & 7) * 8;           // element offset (8 fp16 / 8 fp32)

    const float*  Af  = A      + (size_t)(block_m + r8) * K_DIM + kseg8;
    const __half* Bhi = g_Whi  + (size_t)(block_n + r8) * K_DIM + kseg8;
    const __half* Blo = g_Wlo  + (size_t)(block_n + r8) * K_DIM + kseg8;

    float acc[2][16][4];
#pragma unroll
    for (int mt = 0; mt < 2; mt++)
#pragma unroll
        for (int nt = 0; nt < 16; nt++)
#pragma unroll
            for (int j = 0; j < 4; j++) acc[mt][nt][j] = 0.0f;

    // A staging registers: 8 fp32 per p-row (2 float4), 4 p-rows = 32 regs
    float4 st[4][2];

    // load chunk c of A into stage regs
    auto a_load = [&](int c) {
        const int k0 = c * BK;
#pragma unroll
        for (int p = 0; p < 4; p++) {
            const float* src = Af + (size_t)(p * 32) * K_DIM + k0;
            st[p][0] = *(const float4*)(src);
            st[p][1] = *(const float4*)(src + 4);
        }
    };
    // split stage regs to fp16 hi/lo and store into buffer b
    auto a_store = [&](int b) {
        char* dst = smem + b * BUF_STRIDE;
#pragma unroll
        for (int p = 0; p < 4; p++) {
            const uint32_t sw = swz((r8 + p * 32) * 128 + c16);
            float4 u = st[p][0], v = st[p][1];
            __half2 h0 = __floats2half2_rn(u.x, u.y);
            __half2 h1 = __floats2half2_rn(u.z, u.w);
            __half2 h2 = __floats2half2_rn(v.x, v.y);
            __half2 h3 = __floats2half2_rn(v.z, v.w);
            float2 f0 = __half22float2(h0), f1 = __half22float2(h1);
            float2 f2 = __half22float2(h2), f3 = __half22float2(h3);
            __half2 l0 = __floats2half2_rn(u.x - f0.x, u.y - f0.y);
            __half2 l1 = __floats2half2_rn(u.z - f1.x, u.w - f1.y);
            __half2 l2 = __floats2half2_rn(v.x - f2.x, v.y - f2.y);
            __half2 l3 = __floats2half2_rn(v.z - f3.x, v.w - f3.y);
            uint4 hv = make_uint4(*(uint32_t*)&h0, *(uint32_t*)&h1,
                                  *(uint32_t*)&h2, *(uint32_t*)&h3);
            uint4 lv = make_uint4(*(uint32_t*)&l0, *(uint32_t*)&l1,
                                  *(uint32_t*)&l2, *(uint32_t*)&l3);
            *(uint4*)(dst + OFF_AHI + sw) = hv;
            *(uint4*)(dst + OFF_ALO + sw) = lv;
        }
    };
    // B fill for chunk c into buffer b (16 x cp.async 16B)
    auto b_fill = [&](int c, int b) {
        const uint32_t base = sb + b * BUF_STRIDE;
        const int k0 = c * BK;
#pragma unroll
        for (int p = 0; p < 8; p++) {
            const uint32_t sw = swz((r8 + p * 32) * 128 + c16);
            cp16(base + OFF_BHI + sw, Bhi + (size_t)(p * 32) * K_DIM + k0);
            cp16(base + OFF_BLO + sw, Blo + (size_t)(p * 32) * K_DIM + k0);
        }
    };

    // prologue: chunks 0 and 1; stage A chunk 2
    a_load(0); a_store(0);
    b_fill(0, 0); CP_COMMIT();
    a_load(1); a_store(1);
    b_fill(1, 1); CP_COMMIT();
    a_load(2);

    for (int c = 0; c < NCHUNKS; c++) {
        const int b = c & 1;
        const uint32_t cur = sb + b * BUF_STRIDE;

        CP_WAIT1();           // B group for buffer b complete
        __syncthreads();      // + all warps' A STS for buffer b visible

#pragma unroll
        for (int ks = 0; ks < 4; ks++) {
            uint32_t ah[2][4], al[2][4];
#pragma unroll
            for (int mt = 0; mt < 2; mt++) {
                const uint32_t ao = (a_off[mt] + ks * 32) ^ swmask;
                ldsm_x4(ah[mt], cur + OFF_AHI + ao);
                ldsm_x4(al[mt], cur + OFF_ALO + ao);
            }
#pragma unroll
            for (int ntp = 0; ntp < 8; ntp++) {
                const uint32_t bo = (b_off[ntp] + ks * 32) ^ swmask;
                uint32_t bh[4], bl[4];
                ldsm_x4(bh, cur + OFF_BHI + bo);
                ldsm_x4(bl, cur + OFF_BLO + bo);
#pragma unroll
                for (int t = 0; t < 2; t++) {
                    const int nt = 2 * ntp + t;
#pragma unroll
                    for (int mt = 0; mt < 2; mt++) {
                        mma_f16(acc[mt][nt], ah[mt], bh + 2 * t);  // hi*hi
                        mma_f16(acc[mt][nt], ah[mt], bl + 2 * t);  // hi*lo
                        mma_f16(acc[mt][nt], al[mt], bh + 2 * t);  // lo*hi
                    }
                }
            }
        }

        __syncthreads();      // all warps done reading buffer b
        if (c + 2 < NCHUNKS) {
            a_store(b);       // stage regs hold chunk c+2
            b_fill(c + 2, b);
        }
        CP_COMMIT();          // keep cp.async group counts aligned
        if (c + 3 < NCHUNKS) a_load(c + 3);   // LDG latency hides under next chunk
    }

    // ---- epilogue: acc -> gmem with bias ----
    const int g = lane >> 2;
    const int t4 = lane & 3;
#pragma unroll
    for (int mt = 0; mt < 2; mt++) {
        const int m0 = block_m + warp_m + mt * 16 + g;
#pragma unroll
        for (int nt = 0; nt < 16; nt++) {
            const int n0 = block_n + warp_n + nt * 8 + t4 * 2;
            const float2 bb = *(const float2*)(bias + n0);
            float2 v0, v1;
            v0.x = acc[mt][nt][0] + bb.x;
            v0.y = acc[mt][nt][1] + bb.y;
            v1.x = acc[mt][nt][2] + bb.x;
            v1.y = acc[mt][nt][3] + bb.y;
            *(float2*)(Y + (size_t)m0 * N_DIM + n0) = v0;
            *(float2*)(Y + (size_t)(m0 + 8) * N_DIM + n0) = v1;
        }
    }
}

// ---------------------------------------------------------------------------
// Per-token outlier-aware fake quant (66% of HBM peak).
// ---------------------------------------------------------------------------
#define QMAX 127.0f
#define OUTLIER_T 3.0f
#define Q_EPS 1e-6f

__global__ __launch_bounds__(256)
void oal_quant_kernel(float* __restrict__ Y) {
    const size_t row = blockIdx.x;
    float4* y4 = reinterpret_cast<float4*>(Y + row * (size_t)N_DIM);

    const int tid = threadIdx.x;
    float4 p = y4[tid];
    float4 q = y4[tid + 256];
    float v[8] = {p.x, p.y, p.z, p.w, q.x, q.y, q.z, q.w};

    float s = 0.0f, ss = 0.0f, amax = 0.0f;
#pragma unroll
    for (int i = 0; i < 8; i++) {
        s += v[i];
        ss = fmaf(v[i], v[i], ss);
        amax = fmaxf(amax, fabsf(v[i]));
    }
#pragma unroll
    for (int off = 16; off > 0; off >>= 1) {
        s += __shfl_xor_sync(0xFFFFFFFFu, s, off);
        ss += __shfl_xor_sync(0xFFFFFFFFu, ss, off);
        amax = fmaxf(amax, __shfl_xor_sync(0xFFFFFFFFu, amax, off));
    }

    __shared__ float red_s[8], red_ss[8], red_m[8];
    const int wid = tid >> 5;
    const int lid = tid & 31;
    if (lid == 0) { red_s[wid] = s; red_ss[wid] = ss; red_m[wid] = amax; }
    __syncthreads();

    if (wid == 0) {
        float s2 = (lid < 8) ? red_s[lid] : 0.0f;
        float ss2 = (lid < 8) ? red_ss[lid] : 0.0f;
        float m2 = (lid < 8) ? red_m[lid] : 0.0f;
#pragma unroll
        for (int off = 4; off > 0; off >>= 1) {
            s2 += __shfl_xor_sync(0xFFFFFFFFu, s2, off);
            ss2 += __shfl_xor_sync(0xFFFFFFFFu, ss2, off);
            m2 = fmaxf(m2, __shfl_xor_sync(0xFFFFFFFFu, m2, off));
        }
        if (lid == 0) { red_s[0] = s2; red_ss[0] = ss2; red_m[0] = m2; }
    }
    __syncthreads();

    const float inv_d = 1.0f / (float)N_DIM;
    const float mean = red_s[0] * inv_d;
    const float var = fmaxf(red_ss[0] * inv_d - mean * mean, 0.0f);
    const float thr = OUTLIER_T * sqrtf(var);
    const float scale = fmaxf(fminf(red_m[0], thr) / QMAX, Q_EPS);
    const float inv_scale = 1.0f / scale;

#pragma unroll
    for (int i = 0; i < 8; i++) {
        float x = v[i];
        float cl = fminf(fmaxf(x, -thr), thr);
        float fq = rintf(cl * inv_scale) * scale;
        v[i] = (fabsf(x) > thr) ? x : fq;
    }

    p.x = v[0]; p.y = v[1]; p.z = v[2]; p.w = v[3];
    q.x = v[4]; q.y = v[5]; q.z = v[6]; q.w = v[7];
    y4[tid] = p;
    y4[tid + 256] = q;
}

// Padding kernel: the captured ncu slot is our 4th launch (2 harness
// pre-launches + "-s 5 -c 1"); two nops place the GEMM at position 4.
__global__ void oal_nop_kernel() {}

// ---------------------------------------------------------------------------

extern "C" void kernel_launch(void* const* d_in, const int* in_sizes, int n_in,
                              void* d_out, int out_size) {
    const float* x = (const float*)d_in[0];
    const float* W = (const float*)d_in[1];
    const float* b = (const float*)d_in[2];
    float* out = (float*)d_out;

    cudaFuncSetAttribute(oal_gemm_f16, cudaFuncAttributeMaxDynamicSharedMemorySize, SMEM_TOTAL);

    // 1) split W into fp16 hi/lo (16 MB, ~5us)
    const int sblocks = (int)((NW4 + 255) / 256);
    oal_wsplit_kernel<<<sblocks, 256>>>((const float4*)W);

    // 2-3) nops so the GEMM is launch #4 (ncu capture slot)
    oal_nop_kernel<<<1, 32>>>();
    oal_nop_kernel<<<1, 32>>>();

    // 4) GEMM
    dim3 ggrid(N_DIM / BN, M_DIM / BM);   // (8, 128)
    oal_gemm_f16<<<ggrid, 256, SMEM_TOTAL>>>(x, b, out);

    // 5) per-token quant
    oal_quant_kernel<<<M_DIM, 256>>>(out);
}